// round 16
// baseline (speedup 1.0000x reference)
#include <cuda_runtime.h>
#include <stdint.h>

#define B_DIM 4
#define C_DIM 2
#define E_DIM 256
#define L_DIM 16000
#define W_DIM 40
#define STEP  20
#define T_DIM ((L_DIM - 1) * STEP + W_DIM)   // 320020
#define NT    128
#define MTILE 64                   // l's per CTA
#define LTILES (L_DIM / MTILE)     // 250
#define NCTAS (B_DIM * LTILES)     // 1000

#define KC      16
#define NSTAGE  (E_DIM / KC)       // 16
#define NBUF    3
#define PITCH_A 72                 // words; mod 32 == 8 -> conflict-free frag reads
#define PITCH_B 20                 // words; (nt*8+g)*20 + tig distinct mod 32
#define PITCH_D 40

#define SA_WORDS (KC * PITCH_A)        // 1152 per buffer
#define SB_WORDS (W_DIM * PITCH_B)     // 800 per buffer
#define MIX_OFF  0                                  // 3 bufs
#define MSK_OFF  (NBUF * SA_WORDS)                  // 3456; 3 bufs x 2 channels
#define BAS_OFF  (MSK_OFF + 2 * NBUF * SA_WORDS)    // 10368
#define LOOP_WORDS (BAS_OFF + NBUF * SB_WORDS)      // 12768
#define SMEM_BYTES (LOOP_WORDS * 4)                 // 51072

// ---- inter-CTA boundary mailbox (producer bid -> consumer bid+4) ----
__device__ float g_bnd[NCTAS * C_DIM * STEP];   // producer's last-row upper halves
__device__ int   g_flag[NCTAS];                 // zero-init at module load; consumer resets

__device__ __forceinline__ uint32_t f2tf32(float f) {
    uint32_t u;
    asm("cvt.rna.tf32.f32 %0, %1;" : "=r"(u) : "f"(f));
    return u;
}
__device__ __forceinline__ void mma_tf32(float* d, const uint32_t* a, const uint32_t* b) {
    asm volatile(
        "mma.sync.aligned.m16n8k8.row.col.f32.tf32.tf32.f32 "
        "{%0,%1,%2,%3}, {%4,%5,%6,%7}, {%8,%9}, {%0,%1,%2,%3};"
        : "+f"(d[0]), "+f"(d[1]), "+f"(d[2]), "+f"(d[3])
        : "r"(a[0]), "r"(a[1]), "r"(a[2]), "r"(a[3]), "r"(b[0]), "r"(b[1]));
}
__device__ __forceinline__ void cp16(uint32_t dst_smem, const void* src) {
    asm volatile("cp.async.cg.shared.global [%0], [%1], 16;" :: "r"(dst_smem), "l"(src));
}
__device__ __forceinline__ void cp_commit() {
    asm volatile("cp.async.commit_group;" ::: "memory");
}
__device__ __forceinline__ void cp_wait1() {
    asm volatile("cp.async.wait_group 1;" ::: "memory");
}

__global__ void __launch_bounds__(NT, 4)
decoder_kernel(const float* __restrict__ mix,
               const float* __restrict__ mask,
               const float* __restrict__ basis,
               float* __restrict__ out) {
    extern __shared__ __align__(16) uint32_t smem[];
    const uint32_t smem_base = (uint32_t)__cvta_generic_to_shared(smem);
    float* sF = reinterpret_cast<float*>(smem);
    float* sD = sF;                                  // epilogue overlay (2*64*40 words)

    const int tid  = threadIdx.x;
    const int wid  = tid >> 5;
    const int lane = tid & 31;
    const int g    = lane >> 2;
    const int tig  = lane & 3;

    const int bid   = blockIdx.x;
    const int b     = bid & 3;
    const int ltile = bid >> 2;

    const float* pmix = mix + (size_t)b * E_DIM * L_DIM + (size_t)ltile * MTILE;
    const float* pmk0 = mask + ((size_t)b * C_DIM + 0) * E_DIM * L_DIM + (size_t)ltile * MTILE;
    const float* pmk1 = pmk0 + (size_t)E_DIM * L_DIM;

    // staging coords: mix -> 2 quads/thread; mask -> my channel, 4 quads/thread
    const int mch = tid >> 6;              // which mask channel this thread stages
    const int mt6 = tid & 63;
    const float* pmk = (mch == 0) ? pmk0 : pmk1;

    float acc[2][5][4];
#pragma unroll
    for (int mt = 0; mt < 2; ++mt)
#pragma unroll
        for (int nt = 0; nt < 5; ++nt)
#pragma unroll
            for (int r = 0; r < 4; ++r) acc[mt][nt][r] = 0.f;

    // ---- stage issuer (cp.async) ----
    auto issue_stage = [&](int s) {
        if (s < NSTAGE) {
            const int buf = s % NBUF;
            const size_t eoff = (size_t)s * KC * L_DIM;
            const uint32_t dmix = smem_base + (MIX_OFF + buf * SA_WORDS) * 4;
            const uint32_t dmsk = smem_base + (MSK_OFF + (buf * 2 + mch) * SA_WORDS) * 4;
            // mix: 256 quads over 128 threads (2 each); 16 quads per e-row
#pragma unroll
            for (int i = 0; i < 2; ++i) {
                const int q = tid + (i << 7);
                const int e = q >> 4, l4 = (q & 15) * 4;
                cp16(dmix + (uint32_t)(e * PITCH_A + l4) * 4,
                     pmix + eoff + (size_t)e * L_DIM + l4);
            }
            // mask (my channel): 256 quads over 64 threads (4 each)
#pragma unroll
            for (int i = 0; i < 4; ++i) {
                const int q = mt6 + (i << 6);
                const int e = q >> 4, l4 = (q & 15) * 4;
                cp16(dmsk + (uint32_t)(e * PITCH_A + l4) * 4,
                     pmk + eoff + (size_t)e * L_DIM + l4);
            }
            // basis chunk: 160 quads over 128 threads (1 each + 32 extra)
            {
                const uint32_t dbas = smem_base + (BAS_OFF + buf * SB_WORDS) * 4;
                const int w = tid >> 2, be = (tid & 3) * 4;
                cp16(dbas + (uint32_t)(w * PITCH_B + be) * 4,
                     basis + (size_t)w * E_DIM + s * KC + be);
                if (tid < 32) {
                    const int q2 = 128 + tid;
                    const int w2 = q2 >> 2, be2 = (q2 & 3) * 4;
                    cp16(dbas + (uint32_t)(w2 * PITCH_B + be2) * 4,
                         basis + (size_t)w2 * E_DIM + s * KC + be2);
                }
            }
        }
        cp_commit();   // empty groups past the end keep wait counts uniform
    };

    // prologue: stages 0 and 1 in flight
    issue_stage(0);
    issue_stage(1);

    const int ch    = wid >> 1;            // compute channel of this warp
    const int mbase = (wid & 1) * 32;

#pragma unroll 1
    for (int st = 0; st < NSTAGE; ++st) {
        cp_wait1();                 // stage st landed (st+1 still in flight)
        __syncthreads();            // stage st visible; all warps past mma(st-1)
        issue_stage(st + 2);        // buf (st+2)%3 == (st-1)%3: freed by the sync above

        const int buf = st % NBUF;
        const float* fMix = sF + MIX_OFF + buf * SA_WORDS;
        const float* fMsk = sF + MSK_OFF + (buf * 2 + ch) * SA_WORDS;
        const float* fB   = sF + BAS_OFF + buf * SB_WORDS;

#pragma unroll
        for (int ks = 0; ks < 2; ++ks) {
            const int kb = ks * 8;
            const int r1 = (kb + tig) * PITCH_A;
            const int r2 = (kb + tig + 4) * PITCH_A;
            uint32_t a[2][4];
#pragma unroll
            for (int mt = 0; mt < 2; ++mt) {
                const int m0 = mbase + mt * 16 + g;
                a[mt][0] = f2tf32(fMix[r1 + m0]     * fMsk[r1 + m0]);
                a[mt][1] = f2tf32(fMix[r1 + m0 + 8] * fMsk[r1 + m0 + 8]);
                a[mt][2] = f2tf32(fMix[r2 + m0]     * fMsk[r2 + m0]);
                a[mt][3] = f2tf32(fMix[r2 + m0 + 8] * fMsk[r2 + m0 + 8]);
            }
            uint32_t bf[5][2];
#pragma unroll
            for (int nt = 0; nt < 5; ++nt) {
                bf[nt][0] = f2tf32(fB[(nt * 8 + g) * PITCH_B + kb + tig]);
                bf[nt][1] = f2tf32(fB[(nt * 8 + g) * PITCH_B + kb + tig + 4]);
            }
#pragma unroll
            for (int mt = 0; mt < 2; ++mt)
#pragma unroll
                for (int nt = 0; nt < 5; ++nt)
                    mma_tf32(acc[mt][nt], a[mt], bf[nt]);
        }
    }

    // ---- write frags to D tile in SMEM (overlay; loop buffers dead) ----
    __syncthreads();
#pragma unroll
    for (int mt = 0; mt < 2; ++mt) {
#pragma unroll
        for (int nt = 0; nt < 5; ++nt) {
            int row = ch * MTILE + mbase + mt * 16 + g;
            int col = nt * 8 + 2 * tig;
            *reinterpret_cast<float2*>(&sD[row * PITCH_D + col]) =
                make_float2(acc[mt][nt][0], acc[mt][nt][1]);
            *reinterpret_cast<float2*>(&sD[(row + 8) * PITCH_D + col]) =
                make_float2(acc[mt][nt][2], acc[mt][nt][3]);
        }
    }
    __syncthreads();

    // ---- PRODUCE: publish last-row upper halves (both channels) to the mailbox ----
    if (ltile < LTILES - 1) {
        if (tid < C_DIM * STEP) {
            const int pch = tid / STEP, j = tid % STEP;
            g_bnd[(bid * C_DIM + pch) * STEP + j] =
                sD[(pch * MTILE + MTILE - 1) * PITCH_D + STEP + j];
        }
        __syncthreads();
        if (tid == 0) {
            __threadfence();
            atomicExch(&g_flag[bid], 1);    // release
        }
    }

    // ---- CONSUME + overlap-add epilogue: all plain stores, no atomics on out ----
    const int r  = tid & 63;
    const int rr = mch * MTILE + r;        // sD row
    const int l  = ltile * MTILE + r;

    float lo[STEP], up[STEP];
#pragma unroll
    for (int q = 0; q < 5; ++q) {
        float4 v = *reinterpret_cast<float4*>(&sD[rr * PITCH_D + q * 4]);
        lo[4 * q] = v.x; lo[4 * q + 1] = v.y; lo[4 * q + 2] = v.z; lo[4 * q + 3] = v.w;
    }
    if (r > 0) {
#pragma unroll
        for (int q = 0; q < 5; ++q) {
            float4 v = *reinterpret_cast<float4*>(&sD[(rr - 1) * PITCH_D + STEP + q * 4]);
            up[4 * q] = v.x; up[4 * q + 1] = v.y; up[4 * q + 2] = v.z; up[4 * q + 3] = v.w;
        }
    } else if (ltile > 0) {
        // spin for producer bid-4 (scheduled no later than us; publishes before consuming)
        const int p = bid - 4;
        while (atomicAdd(&g_flag[p], 0) == 0) {}
        __threadfence();                    // acquire
#pragma unroll
        for (int j = 0; j < STEP; ++j)
            up[j] = g_bnd[(p * C_DIM + mch) * STEP + j];
    } else {
#pragma unroll
        for (int j = 0; j < STEP; ++j) up[j] = 0.f;   // l==0: no predecessor
    }

    const size_t base = ((size_t)b * C_DIM + mch) * T_DIM + (size_t)l * STEP;
#pragma unroll
    for (int j = 0; j < STEP; ++j) out[base + j] = lo[j] + up[j];

    if (r == MTILE - 1 && l == L_DIM - 1) {   // global tail: sole contributor
#pragma unroll
        for (int q = 0; q < 5; ++q) {
            float4 v = *reinterpret_cast<float4*>(&sD[rr * PITCH_D + STEP + q * 4]);
            out[base + STEP + 4 * q]     = v.x;
            out[base + STEP + 4 * q + 1] = v.y;
            out[base + STEP + 4 * q + 2] = v.z;
            out[base + STEP + 4 * q + 3] = v.w;
        }
    }

    // ---- reset consumed flag so the next graph replay starts clean ----
    __syncthreads();                        // both consumers (tid 0,64) done reading
    if (tid == 0 && ltile > 0) g_flag[bid - 4] = 0;
}

extern "C" void kernel_launch(void* const* d_in, const int* in_sizes, int n_in,
                              void* d_out, int out_size) {
    // Identify inputs by element count for robustness.
    const float *mix = nullptr, *mask = nullptr, *basis = nullptr;
    for (int i = 0; i < n_in; ++i) {
        long long s = in_sizes[i];
        if (s == (long long)B_DIM * E_DIM * L_DIM)              mix   = (const float*)d_in[i];
        else if (s == (long long)B_DIM * C_DIM * E_DIM * L_DIM) mask  = (const float*)d_in[i];
        else if (s == (long long)W_DIM * E_DIM)                 basis = (const float*)d_in[i];
    }
    float* out = (float*)d_out;

    cudaFuncSetAttribute(decoder_kernel,
                         cudaFuncAttributeMaxDynamicSharedMemorySize, SMEM_BYTES);
    decoder_kernel<<<NCTAS, NT, SMEM_BYTES>>>(mix, mask, basis, out);
}